// round 12
// baseline (speedup 1.0000x reference)
#include <cuda_runtime.h>
#include <cstdint>

typedef unsigned long long ull;

#define NPTS 16384
#define NPER 8192
#define MQ   4096
#define NS   32
#define OD   256
#define CG   131

// ---------------- device scratch (no runtime allocation allowed) -------------
__device__ float g_featsT[NPTS * 128];   // [point][channel]
__device__ float g_keyT[CG * OD];        // [c][o]
__device__ float g_v1T [CG * OD];
__device__ float g_v2T [OD * OD];
__device__ float g_kcT [OD * OD];
__device__ float g_qcT [OD * OD];
__device__ float g_qkcT[OD * OD];
__device__ float g_vcT [OD * OD];
__device__ float g_clsT[OD * 128];       // [c][t]
__device__ float g_regT[OD * 128];
__device__ int   g_idx [MQ * NS];

// ---------------- packed fp32x2 helpers --------------------------------------
__device__ __forceinline__ void ffma2(ull& d, ull a, ull b) {
    asm("fma.rn.f32x2 %0, %1, %2, %0;" : "+l"(d) : "l"(a), "l"(b));
}
__device__ __forceinline__ ull pack2(float x) {
    ull r; unsigned xi = __float_as_uint(x);
    asm("mov.b64 %0, {%1, %2};" : "=l"(r) : "r"(xi), "r"(xi));
    return r;
}
__device__ __forceinline__ float2 unpack2(ull v) {
    unsigned lo, hi;
    asm("mov.b64 {%0, %1}, %2;" : "=r"(lo), "=r"(hi) : "l"(v));
    return make_float2(__uint_as_float(lo), __uint_as_float(hi));
}
__device__ __forceinline__ float sigf(float x) { return 1.f / (1.f + expf(-x)); }

// ---------------- weight transposes ------------------------------------------
__global__ void wprep_kernel(const float* __restrict__ key_w, const float* __restrict__ v1w,
                             const float* __restrict__ v2w,  const float* __restrict__ kcw,
                             const float* __restrict__ qcw,  const float* __restrict__ qkcw,
                             const float* __restrict__ vcw,  const float* __restrict__ cw1,
                             const float* __restrict__ rw1) {
    int i = blockIdx.x * 256 + threadIdx.x;
    if (i < OD * OD) {
        int c = i >> 8, o = i & 255;
        g_v2T[i]  = v2w[o * OD + c];
        g_kcT[i]  = kcw[o * OD + c];
        g_qcT[i]  = qcw[o * OD + c];
        g_qkcT[i] = qkcw[o * OD + c];
        g_vcT[i]  = vcw[o * OD + c];
    }
    if (i < CG * OD) {
        int c = i >> 8, o = i & 255;
        g_keyT[i] = key_w[o * CG + c];
        g_v1T[i]  = v1w[o * CG + c];
    }
    if (i < OD * 128) {
        int c = i >> 7, t = i & 127;
        g_clsT[i] = cw1[t * OD + c];
        g_regT[i] = rw1[t * OD + c];
    }
}

// ---------------- feature transpose [B][C][N] -> [point][C] ------------------
__global__ void tfeat_kernel(const float* __restrict__ f) {
    __shared__ float t[32][33];
    int b = blockIdx.z, ct = blockIdx.y * 32, nt = blockIdx.x * 32;
    int x = threadIdx.x, y = threadIdx.y;
    #pragma unroll
    for (int r = 0; r < 32; r += 8)
        t[y + r][x] = f[((size_t)(b * 128 + ct + y + r)) * NPER + nt + x];
    __syncthreads();
    #pragma unroll
    for (int r = 0; r < 32; r += 8)
        g_featsT[(size_t)(b * NPER + nt + y + r) * 128 + ct + x] = t[x][y + r];
}

// ---------------- ball query (warp per query, first-32-by-index) -------------
__global__ __launch_bounds__(256) void ball_kernel(const float* __restrict__ xyz,
                                                   const float* __restrict__ nxyz) {
    __shared__ int sbuf[8][NS];
    int warp = threadIdx.x >> 5, lane = threadIdx.x & 31;
    int m = blockIdx.x * 8 + warp;
    const float R2 = 2.5600001f * 0.99999994f; // == float(1.6*1.6)
    float r2 = __fmul_rn(1.6f, 1.6f);
    (void)R2;
    float qx = nxyz[m * 3 + 0], qy = nxyz[m * 3 + 1], qz = nxyz[m * 3 + 2];
    int count = 0;
    for (int base = 0; base < NPTS; base += 32) {
        int p = base + lane;
        float dx = __fadd_rn(xyz[p * 3 + 0], -qx);
        float dy = __fadd_rn(xyz[p * 3 + 1], -qy);
        float dz = __fadd_rn(xyz[p * 3 + 2], -qz);
        float d2 = __fadd_rn(__fadd_rn(__fmul_rn(dx, dx), __fmul_rn(dy, dy)),
                             __fmul_rn(dz, dz));
        unsigned msk = __ballot_sync(0xffffffffu, d2 < r2);
        int slot = count + __popc(msk & ((1u << lane) - 1u));
        if ((msk >> lane & 1u) && slot < NS) sbuf[warp][slot] = p;
        count += __popc(msk);
        if (count >= NS) break;          // warp-uniform
    }
    __syncwarp();
    int v = 0;
    if (count > 0) v = (lane < count) ? sbuf[warp][lane] : sbuf[warp][0];
    g_idx[m * NS + lane] = v;
}

// ---------------- main fused kernel ------------------------------------------
// smem layout (float offsets)
#define OFF_GF   0        // 131*32
#define OFF_VB   4192     // 256*36 (stride 36)
#define OFF_KB   13408    // 256*36
#define OFF_PM   22624
#define OFF_KM   22880
#define OFF_PKM  23136
#define OFF_CTX  23392    // [vc|qc|kc|qkc] * 256
#define OFF_AW   24416    // 4*256
#define OFF_NF   25440
#define OFF_HID  25696
#define OFF_ATT  25952    // 4*32
#define OFF_MISC 26080    // q(3), gates(4..5), idx ints at +8
#define SM_FLOATS 26120
#define BNS 0.99999500003749987f   // 1/sqrt(1+1e-5)

__global__ __launch_bounds__(256, 2) void main_kernel(
    const float* __restrict__ xyz,  const float* __restrict__ nxyz,
    const float* __restrict__ pos_w,
    const float* __restrict__ bn1g, const float* __restrict__ bn1b,
    const float* __restrict__ bn2g, const float* __restrict__ bn2b,
    const float* __restrict__ attn_w,
    const float* __restrict__ cb1,  const float* __restrict__ cw2,
    const float* __restrict__ cb2,  const float* __restrict__ rb1,
    const float* __restrict__ rw2,  const float* __restrict__ rb2,
    float* __restrict__ out)
{
    extern __shared__ float sm[];
    const int m = blockIdx.x, tid = threadIdx.x;
    int* sidx = (int*)(sm + OFF_MISC + 8);
    if (tid < 32) sidx[tid] = g_idx[m * NS + tid];
    if (tid >= 32 && tid < 35) sm[OFF_MISC + tid - 32] = nxyz[m * 3 + tid - 32];
    sm[OFF_AW + tid]       = attn_w[tid];
    sm[OFF_AW + 256 + tid] = attn_w[256 + tid];
    sm[OFF_AW + 512 + tid] = attn_w[512 + tid];
    sm[OFF_AW + 768 + tid] = attn_w[768 + tid];
    __syncthreads();

    // ---- gather gf = [gx(3) ; feats(128)] rows, [c][n] layout -----------
    {
        int part = tid >> 5, n = tid & 31;
        int p = sidx[n];
        const float4* src = (const float4*)(g_featsT + (size_t)p * 128 + part * 16);
        #pragma unroll
        for (int k = 0; k < 4; k++) {
            float4 v = src[k];
            int c = 3 + part * 16 + k * 4;
            sm[OFF_GF + c * 32 + n]       = v.x;
            sm[OFF_GF + (c + 1) * 32 + n] = v.y;
            sm[OFF_GF + (c + 2) * 32 + n] = v.z;
            sm[OFF_GF + (c + 3) * 32 + n] = v.w;
        }
        if (part == 0) {
            float qx = sm[OFF_MISC], qy = sm[OFF_MISC + 1], qz = sm[OFF_MISC + 2];
            sm[OFF_GF + n]      = xyz[p * 3 + 0] - qx;
            sm[OFF_GF + 32 + n] = xyz[p * 3 + 1] - qy;
            sm[OFF_GF + 64 + n] = xyz[p * 3 + 2] - qz;
        }
    }
    __syncthreads();

    const int o = tid;
    // ---- fused key & val1 GEMM over c (packed f32x2, prefetch 2) --------
    ull ka[16], va[16];
    #pragma unroll
    for (int j = 0; j < 16; j++) { ka[j] = 0ull; va[j] = 0ull; }
    {
        const float* kw = g_keyT + o;
        const float* vw = g_v1T + o;
        float k0 = __ldg(kw), v0 = __ldg(vw);
        float k1 = __ldg(kw + OD), v1 = __ldg(vw + OD);
        for (int c = 0; c < CG; c++) {
            float kn = 0.f, vn = 0.f;
            if (c + 2 < CG) { kn = __ldg(kw + (c + 2) * OD); vn = __ldg(vw + (c + 2) * OD); }
            ull kp = pack2(k0), vp = pack2(v0);
            const ulonglong2* row = (const ulonglong2*)(sm + OFF_GF + c * 32);
            #pragma unroll
            for (int j = 0; j < 8; j++) {
                ulonglong2 u = row[j];
                ffma2(ka[2 * j], kp, u.x); ffma2(ka[2 * j + 1], kp, u.y);
                ffma2(va[2 * j], vp, u.x); ffma2(va[2 * j + 1], vp, u.y);
            }
            k0 = k1; v0 = v1; k1 = kn; v1 = vn;
        }
    }
    // ---- epilogue: key -> keybuf, v=relu(bn1) -> vbuf, means ------------
    {
        float g1 = bn1g[o], b1 = bn1b[o];
        float pw0 = pos_w[o * 3], pw1 = pos_w[o * 3 + 1], pw2 = pos_w[o * 3 + 2];
        float4* kb = (float4*)(sm + OFF_KB + o * 36);
        float4* vb = (float4*)(sm + OFF_VB + o * 36);
        float ps = 0.f, ks = 0.f, pks = 0.f;
        #pragma unroll
        for (int j = 0; j < 8; j++) {
            float2 kx = unpack2(ka[2 * j]), ky = unpack2(ka[2 * j + 1]);
            float4 kk = make_float4(fmaxf(kx.x, 0.f), fmaxf(kx.y, 0.f),
                                    fmaxf(ky.x, 0.f), fmaxf(ky.y, 0.f));
            kb[j] = kk;
            float2 vx = unpack2(va[2 * j]), vy = unpack2(va[2 * j + 1]);
            float4 vv = make_float4(fmaxf(fmaf(g1, vx.x * BNS, b1), 0.f),
                                    fmaxf(fmaf(g1, vx.y * BNS, b1), 0.f),
                                    fmaxf(fmaf(g1, vy.x * BNS, b1), 0.f),
                                    fmaxf(fmaf(g1, vy.y * BNS, b1), 0.f));
            vb[j] = vv;
            float kv[4] = {kk.x, kk.y, kk.z, kk.w};
            #pragma unroll
            for (int t = 0; t < 4; t++) {
                int n = 4 * j + t;
                float pn = fmaxf(fmaf(pw0, sm[OFF_GF + n],
                             fmaf(pw1, sm[OFF_GF + 32 + n],
                                  pw2 * sm[OFF_GF + 64 + n])), 0.f);
                ps += pn; ks += kv[t]; pks += pn * kv[t];
            }
        }
        sm[OFF_PM + o]  = ps  * (1.f / 32.f);
        sm[OFF_KM + o]  = ks  * (1.f / 32.f);
        sm[OFF_PKM + o] = pks * (1.f / 32.f);
    }
    __syncthreads();

    // ---- ctx matvecs (sigmoid(mean @ W.T)) ------------------------------
    {
        float av = 0.f, aq = 0.f, ak = 0.f, aqk = 0.f;
        const float* wv = g_vcT + o;  const float* wq = g_qcT + o;
        const float* wk = g_kcT + o;  const float* wqk = g_qkcT + o;
        #pragma unroll 4
        for (int c = 0; c < OD; c++) {
            float pm = sm[OFF_PM + c], km = sm[OFF_KM + c], pkm = sm[OFF_PKM + c];
            av  = fmaf(pm,  __ldg(wv  + c * OD), av);
            aq  = fmaf(pm,  __ldg(wq  + c * OD), aq);
            ak  = fmaf(km,  __ldg(wk  + c * OD), ak);
            aqk = fmaf(pkm, __ldg(wqk + c * OD), aqk);
        }
        sm[OFF_CTX + o]       = sigf(av);
        sm[OFF_CTX + 256 + o] = sigf(aq);
        sm[OFF_CTX + 512 + o] = sigf(ak);
        sm[OFF_CTX + 768 + o] = sigf(aqk);
    }

    // ---- val2 GEMM over vbuf --------------------------------------------
    ull wa[16];
    #pragma unroll
    for (int j = 0; j < 16; j++) wa[j] = 0ull;
    {
        const float* w2 = g_v2T + o;
        float w0 = __ldg(w2), w1 = __ldg(w2 + OD);
        for (int c = 0; c < OD; c++) {
            float wn = (c + 2 < OD) ? __ldg(w2 + (c + 2) * OD) : 0.f;
            ull wp = pack2(w0);
            const ulonglong2* row = (const ulonglong2*)(sm + OFF_VB + c * 36);
            #pragma unroll
            for (int j = 0; j < 8; j++) {
                ulonglong2 u = row[j];
                ffma2(wa[2 * j], wp, u.x); ffma2(wa[2 * j + 1], wp, u.y);
            }
            w0 = w1; w1 = wn;
        }
    }
    __syncthreads();   // all vbuf reads done; CTX visible

    // ---- val (regs) + attn_emb -> vbuf ----------------------------------
    float valr[32];
    {
        float g2 = bn2g[o], b2 = bn2b[o];
        float vc  = sm[OFF_CTX + o],       qc  = sm[OFF_CTX + 256 + o];
        float kcv = sm[OFF_CTX + 512 + o], qkc = sm[OFF_CTX + 768 + o];
        float pw0 = pos_w[o * 3], pw1 = pos_w[o * 3 + 1], pw2 = pos_w[o * 3 + 2];
        const float4* kb = (const float4*)(sm + OFF_KB + o * 36);
        float4* eb = (float4*)(sm + OFF_VB + o * 36);
        #pragma unroll
        for (int j = 0; j < 8; j++) {
            float2 a = unpack2(wa[2 * j]), b = unpack2(wa[2 * j + 1]);
            float vv[4] = {a.x, a.y, b.x, b.y};
            float4 kk = kb[j];
            float kv[4] = {kk.x, kk.y, kk.z, kk.w};
            float ef[4];
            #pragma unroll
            for (int t = 0; t < 4; t++) {
                int n = 4 * j + t;
                float pn = fmaxf(fmaf(pw0, sm[OFF_GF + n],
                             fmaf(pw1, sm[OFF_GF + 32 + n],
                                  pw2 * sm[OFF_GF + 64 + n])), 0.f);
                valr[n] = fmaxf(fmaf(g2, vv[t] * BNS, b2), 0.f) + pn * vc;
                ef[t]   = fmaf(pn, qc, fmaf(kv[t], kcv, (pn * kv[t]) * qkc));
            }
            eb[j] = make_float4(ef[0], ef[1], ef[2], ef[3]);
        }
    }
    __syncthreads();

    // ---- logits + softmax (warps 0..3, h = warp) ------------------------
    int wid = tid >> 5, lane = tid & 31;
    if (wid < 4) {
        float s0 = 0.f, s1 = 0.f, s2 = 0.f, s3 = 0.f;
        const float* aw = sm + OFF_AW + wid * 256;
        for (int c = 0; c < OD; c += 4) {
            s0 = fmaf(aw[c],     sm[OFF_VB + c * 36 + lane], s0);
            s1 = fmaf(aw[c + 1], sm[OFF_VB + (c + 1) * 36 + lane], s1);
            s2 = fmaf(aw[c + 2], sm[OFF_VB + (c + 2) * 36 + lane], s2);
            s3 = fmaf(aw[c + 3], sm[OFF_VB + (c + 3) * 36 + lane], s3);
        }
        float lg = (s0 + s1) + (s2 + s3);
        float mx = lg;
        #pragma unroll
        for (int d = 16; d; d >>= 1) mx = fmaxf(mx, __shfl_xor_sync(~0u, mx, d));
        float e = expf(lg - mx);
        float ss = e;
        #pragma unroll
        for (int d = 16; d; d >>= 1) ss += __shfl_xor_sync(~0u, ss, d);
        sm[OFF_ATT + wid * 32 + lane] = e / ss;
    }
    __syncthreads();

    // ---- new_features = sum_n val * attn[h] -----------------------------
    {
        const float* at = sm + OFF_ATT + (o >> 6) * 32;
        float s = 0.f;
        #pragma unroll
        for (int n = 0; n < 32; n++) s = fmaf(valr[n], at[n], s);
        sm[OFF_NF + o] = s;
        out[(size_t)m * OD + o] = s;
    }
    __syncthreads();

    // ---- gate hidden layers ---------------------------------------------
    {
        int t = tid & 127;
        bool isr = tid >= 128;
        const float* wt = (isr ? g_regT : g_clsT) + t;
        float acc = isr ? rb1[t] : cb1[t];
        #pragma unroll 4
        for (int c = 0; c < OD; c++)
            acc = fmaf(sm[OFF_NF + c], __ldg(wt + c * 128), acc);
        sm[OFF_HID + tid] = fmaxf(acc, 0.f);
    }
    __syncthreads();
    if (wid < 2) {   // warp0: cls, warp1: reg
        const float* hid = sm + OFF_HID + wid * 128;
        const float* w2p = wid ? rw2 : cw2;
        float s = 0.f;
        #pragma unroll
        for (int k = 0; k < 4; k++)
            s = fmaf(hid[lane + 32 * k], __ldg(w2p + lane + 32 * k), s);
        #pragma unroll
        for (int d = 16; d; d >>= 1) s += __shfl_xor_sync(~0u, s, d);
        if (lane == 0)
            sm[OFF_MISC + 4 + wid] = sigf(s + __ldg(wid ? rb2 : cb2));
    }
    __syncthreads();
    {
        float nf = sm[OFF_NF + o];
        out[(size_t)MQ * OD + (size_t)m * OD + o]     = nf * sm[OFF_MISC + 4];
        out[(size_t)2 * MQ * OD + (size_t)m * OD + o] = nf * sm[OFF_MISC + 5];
    }
}

// ---------------- launch ------------------------------------------------------
extern "C" void kernel_launch(void* const* d_in, const int* in_sizes, int n_in,
                              void* d_out, int out_size) {
    const float* xyz   = (const float*)d_in[0];
    const float* nxyz  = (const float*)d_in[1];
    const float* feats = (const float*)d_in[2];
    const float* pos_w = (const float*)d_in[3];
    const float* key_w = (const float*)d_in[4];
    const float* v1w   = (const float*)d_in[5];
    const float* bn1g  = (const float*)d_in[6];
    const float* bn1b  = (const float*)d_in[7];
    const float* v2w   = (const float*)d_in[8];
    const float* bn2g  = (const float*)d_in[9];
    const float* bn2b  = (const float*)d_in[10];
    const float* attnw = (const float*)d_in[11];
    const float* kcw   = (const float*)d_in[12];
    const float* qcw   = (const float*)d_in[13];
    const float* qkcw  = (const float*)d_in[14];
    const float* vcw   = (const float*)d_in[15];
    const float* cw1   = (const float*)d_in[16];
    const float* cb1   = (const float*)d_in[17];
    const float* cw2   = (const float*)d_in[18];
    const float* cb2   = (const float*)d_in[19];
    const float* rw1   = (const float*)d_in[20];
    const float* rb1   = (const float*)d_in[21];
    const float* rw2   = (const float*)d_in[22];
    const float* rb2   = (const float*)d_in[23];
    float* out = (float*)d_out;

    static bool attr_set = false;
    if (!attr_set) {
        cudaFuncSetAttribute(main_kernel, cudaFuncAttributeMaxDynamicSharedMemorySize,
                             SM_FLOATS * 4);
        attr_set = true;
    }

    wprep_kernel<<<256, 256>>>(key_w, v1w, v2w, kcw, qcw, qkcw, vcw, cw1, rw1);
    tfeat_kernel<<<dim3(256, 4, 2), dim3(32, 8)>>>(feats);
    ball_kernel<<<MQ / 8, 256>>>(xyz, nxyz);
    main_kernel<<<MQ, 256, SM_FLOATS * 4>>>(xyz, nxyz, pos_w, bn1g, bn1b, bn2g, bn2b,
                                            attnw, cb1, cw2, cb2, rb1, rw2, rb2, out);
}

// round 13
// speedup vs baseline: 1.0048x; 1.0048x over previous
#include <cuda_runtime.h>
#include <cstdint>

typedef unsigned long long ull;

#define NPTS 16384
#define NPER 8192
#define MQ   4096
#define OD   256
#define CG   131

// ---------------- device scratch (no runtime allocation allowed) -------------
__device__ float g_featsT[NPTS * 128];        // [point][channel]
__device__ float g_keyT[(CG + 2) * OD];       // [c][o], 2 zero pad rows
__device__ float g_v1T [(CG + 2) * OD];
__device__ float g_v2T [(OD + 2) * OD];
__device__ float g_ctx4[OD * OD * 4];         // [c][o][{vc,qc,kc,qkc}]
__device__ float g_gate4[64 * 256 * 4];       // [c4][col(cls|reg)][4 c]
__device__ int   g_idx [MQ * 32];

// ---------------- packed fp32x2 helpers --------------------------------------
__device__ __forceinline__ void ffma2(ull& d, ull a, ull b) {
    asm("fma.rn.f32x2 %0, %1, %2, %0;" : "+l"(d) : "l"(a), "l"(b));
}
__device__ __forceinline__ ull pack2(float x) {
    ull r; unsigned xi = __float_as_uint(x);
    asm("mov.b64 %0, {%1, %2};" : "=l"(r) : "r"(xi), "r"(xi));
    return r;
}
__device__ __forceinline__ float2 unpack2(ull v) {
    unsigned lo, hi;
    asm("mov.b64 {%0, %1}, %2;" : "=r"(lo), "=r"(hi) : "l"(v));
    return make_float2(__uint_as_float(lo), __uint_as_float(hi));
}
__device__ __forceinline__ float sigf(float x) { return 1.f / (1.f + expf(-x)); }

// ---------------- weight prep ------------------------------------------------
__global__ void wprep_kernel(const float* __restrict__ key_w, const float* __restrict__ v1w,
                             const float* __restrict__ v2w,  const float* __restrict__ kcw,
                             const float* __restrict__ qcw,  const float* __restrict__ qkcw,
                             const float* __restrict__ vcw,  const float* __restrict__ cw1,
                             const float* __restrict__ rw1) {
    int i = blockIdx.x * 256 + threadIdx.x;        // 65536 total
    if (i < OD * OD) {
        int c = i >> 8, o = i & 255;
        g_v2T[i] = v2w[o * OD + c];
        float4 cv = make_float4(vcw[o * OD + c], qcw[o * OD + c],
                                kcw[o * OD + c], qkcw[o * OD + c]);
        *(float4*)(g_ctx4 + (size_t)i * 4) = cv;
    }
    if (i < CG * OD) {
        int c = i >> 8, o = i & 255;
        g_keyT[i] = key_w[o * CG + c];
        g_v1T[i]  = v1w[o * CG + c];
    }
    if (i < 64 * 256) {
        int c4 = i >> 8, col = i & 255;
        const float* src = (col < 128) ? cw1 : rw1;
        int t = col & 127;
        float4 v = make_float4(src[t * OD + c4 * 4],     src[t * OD + c4 * 4 + 1],
                               src[t * OD + c4 * 4 + 2], src[t * OD + c4 * 4 + 3]);
        *(float4*)(g_gate4 + (size_t)i * 4) = v;
    }
}

// ---------------- feature transpose ------------------------------------------
__global__ void tfeat_kernel(const float* __restrict__ f) {
    __shared__ float t[32][33];
    int b = blockIdx.z, ct = blockIdx.y * 32, nt = blockIdx.x * 32;
    int x = threadIdx.x, y = threadIdx.y;
    #pragma unroll
    for (int r = 0; r < 32; r += 8)
        t[y + r][x] = f[((size_t)(b * 128 + ct + y + r)) * NPER + nt + x];
    __syncthreads();
    #pragma unroll
    for (int r = 0; r < 32; r += 8)
        g_featsT[(size_t)(b * NPER + nt + y + r) * 128 + ct + x] = t[x][y + r];
}

// ---------------- ball query -------------------------------------------------
__global__ __launch_bounds__(256) void ball_kernel(const float* __restrict__ xyz,
                                                   const float* __restrict__ nxyz) {
    __shared__ int sbuf[8][32];
    int warp = threadIdx.x >> 5, lane = threadIdx.x & 31;
    int m = blockIdx.x * 8 + warp;
    float r2 = __fmul_rn(1.6f, 1.6f);
    float qx = nxyz[m * 3 + 0], qy = nxyz[m * 3 + 1], qz = nxyz[m * 3 + 2];
    int count = 0;
    for (int base = 0; base < NPTS; base += 32) {
        int p = base + lane;
        float dx = __fadd_rn(xyz[p * 3 + 0], -qx);
        float dy = __fadd_rn(xyz[p * 3 + 1], -qy);
        float dz = __fadd_rn(xyz[p * 3 + 2], -qz);
        float d2 = __fadd_rn(__fadd_rn(__fmul_rn(dx, dx), __fmul_rn(dy, dy)),
                             __fmul_rn(dz, dz));
        unsigned msk = __ballot_sync(0xffffffffu, d2 < r2);
        int slot = count + __popc(msk & ((1u << lane) - 1u));
        if ((msk >> lane & 1u) && slot < 32) sbuf[warp][slot] = p;
        count += __popc(msk);
        if (count >= 32) break;
    }
    __syncwarp();
    int v = 0;
    if (count > 0) v = (lane < count) ? sbuf[warp][lane] : sbuf[warp][0];
    g_idx[m * 32 + lane] = v;
}

// ---------------- main fused kernel ------------------------------------------
#define OFF_GF2  0        // 131*64 duplicated pairs
#define OFF_GX   8384     // 3*32
#define OFF_VB   8480     // 256*36
#define OFF_MI   17696    // 256*4  {pm,km,pkm,pad}
#define OFF_CTX  18720    // 4*256
#define OFF_AWI  19744    // 256*4
#define OFF_PART 20768    // 8*4*32
#define OFF_ATT  21792    // 4*32
#define OFF_NF   21920    // 256
#define OFF_HID  22176    // 256
#define OFF_MISC 22432    // q(0..2), gates(4,5), idx ints at +8
#define SM_FLOATS 22480
#define BNS 0.99999500003749987f

__global__ __launch_bounds__(256, 2) void main_kernel(
    const float* __restrict__ xyz,  const float* __restrict__ nxyz,
    const float* __restrict__ pos_w,
    const float* __restrict__ bn1g, const float* __restrict__ bn1b,
    const float* __restrict__ bn2g, const float* __restrict__ bn2b,
    const float* __restrict__ attn_w,
    const float* __restrict__ cb1,  const float* __restrict__ cw2,
    const float* __restrict__ cb2,  const float* __restrict__ rb1,
    const float* __restrict__ rw2,  const float* __restrict__ rb2,
    float* __restrict__ out)
{
    extern __shared__ float sm[];
    const int m = blockIdx.x, tid = threadIdx.x;
    const int l = tid & 31, w = tid >> 5;
    int* sidx = (int*)(sm + OFF_MISC + 8);
    if (tid < 32) sidx[tid] = g_idx[m * 32 + tid];
    if (tid >= 32 && tid < 35) sm[OFF_MISC + tid - 32] = nxyz[m * 3 + tid - 32];
    #pragma unroll
    for (int h = 0; h < 4; h++) sm[OFF_AWI + tid * 4 + h] = __ldg(attn_w + h * 256 + tid);
    __syncthreads();

    // ---- gather: gf duplicated pairs + plain gx ----
    {
        int part = tid >> 5, n = tid & 31;
        int p = sidx[n];
        const float4* src = (const float4*)(g_featsT + (size_t)p * 128 + part * 16);
        #pragma unroll
        for (int k = 0; k < 4; k++) {
            float4 v = __ldg(src + k);
            int c = 3 + part * 16 + k * 4;
            *(ull*)(sm + OFF_GF2 + (c    ) * 64 + n * 2) = pack2(v.x);
            *(ull*)(sm + OFF_GF2 + (c + 1) * 64 + n * 2) = pack2(v.y);
            *(ull*)(sm + OFF_GF2 + (c + 2) * 64 + n * 2) = pack2(v.z);
            *(ull*)(sm + OFF_GF2 + (c + 3) * 64 + n * 2) = pack2(v.w);
        }
        if (part == 0) {
            float qx = sm[OFF_MISC], qy = sm[OFF_MISC + 1], qz = sm[OFF_MISC + 2];
            float gx = xyz[p * 3 + 0] - qx, gy = xyz[p * 3 + 1] - qy, gz = xyz[p * 3 + 2] - qz;
            sm[OFF_GX + n] = gx; sm[OFF_GX + 32 + n] = gy; sm[OFF_GX + 64 + n] = gz;
            *(ull*)(sm + OFF_GF2 + 0 * 64 + n * 2) = pack2(gx);
            *(ull*)(sm + OFF_GF2 + 1 * 64 + n * 2) = pack2(gy);
            *(ull*)(sm + OFF_GF2 + 2 * 64 + n * 2) = pack2(gz);
        }
    }
    __syncthreads();

    const int og = l >> 2;
    const int o_base = w * 32 + og * 4;
    const int nq = l & 3;
    const int nb = nq * 8;

    // ---- stage 1: key & val1 GEMM (4 o x 8 n per thread) ----
    ull kacc[2][8], vacc[2][8];
    #pragma unroll
    for (int p = 0; p < 2; p++)
        #pragma unroll
        for (int j = 0; j < 8; j++) { kacc[p][j] = 0ull; vacc[p][j] = 0ull; }
    {
        const ulonglong2* kwp = (const ulonglong2*)(g_keyT + o_base);
        const ulonglong2* vwp = (const ulonglong2*)(g_v1T + o_base);
        ulonglong2 k0 = __ldg(kwp),      v0 = __ldg(vwp);
        ulonglong2 k1 = __ldg(kwp + 64), v1 = __ldg(vwp + 64);
        for (int c = 0; c < CG; c++) {
            ulonglong2 k2 = __ldg(kwp + (c + 2) * 64);     // zero-padded rows
            ulonglong2 v2 = __ldg(vwp + (c + 2) * 64);
            const ulonglong2* gp = (const ulonglong2*)(sm + OFF_GF2 + c * 64 + nb * 2);
            ulonglong2 ga = gp[0], gb = gp[1], gc = gp[2], gd = gp[3];
            ull gv[8] = {ga.x, ga.y, gb.x, gb.y, gc.x, gc.y, gd.x, gd.y};
            #pragma unroll
            for (int j = 0; j < 8; j++) {
                ffma2(kacc[0][j], k0.x, gv[j]);
                ffma2(kacc[1][j], k0.y, gv[j]);
                ffma2(vacc[0][j], v0.x, gv[j]);
                ffma2(vacc[1][j], v0.y, gv[j]);
            }
            k0 = k1; v0 = v1; k1 = k2; v1 = v2;
        }
    }

    // ---- epilogue 1: key regs, v -> smem, means via quad butterfly ----
    float key_f[4][8];
    {
        #pragma unroll
        for (int p = 0; p < 2; p++)
            #pragma unroll
            for (int j = 0; j < 8; j++) {
                float2 u = unpack2(kacc[p][j]);
                key_f[2 * p][j]     = fmaxf(u.x, 0.f);
                key_f[2 * p + 1][j] = fmaxf(u.y, 0.f);
            }
        float4 g1 = __ldg((const float4*)(bn1g + o_base));
        float4 b1 = __ldg((const float4*)(bn1b + o_base));
        float g1a[4] = {g1.x, g1.y, g1.z, g1.w};
        float b1a[4] = {b1.x, b1.y, b1.z, b1.w};
        float v_f[4][8];
        #pragma unroll
        for (int p = 0; p < 2; p++)
            #pragma unroll
            for (int j = 0; j < 8; j++) {
                float2 u = unpack2(vacc[p][j]);
                v_f[2 * p][j]     = fmaxf(fmaf(g1a[2 * p],     u.x * BNS, b1a[2 * p]),     0.f);
                v_f[2 * p + 1][j] = fmaxf(fmaf(g1a[2 * p + 1], u.y * BNS, b1a[2 * p + 1]), 0.f);
            }
        #pragma unroll
        for (int i = 0; i < 4; i++) {
            float* dst = sm + OFF_VB + (o_base + i) * 36 + nb;
            *(float4*)(dst)     = make_float4(v_f[i][0], v_f[i][1], v_f[i][2], v_f[i][3]);
            *(float4*)(dst + 4) = make_float4(v_f[i][4], v_f[i][5], v_f[i][6], v_f[i][7]);
        }
        // pos recompute + three means
        float4 x0a = *(const float4*)(sm + OFF_GX + nb);
        float4 x0b = *(const float4*)(sm + OFF_GX + nb + 4);
        float4 x1a = *(const float4*)(sm + OFF_GX + 32 + nb);
        float4 x1b = *(const float4*)(sm + OFF_GX + 32 + nb + 4);
        float4 x2a = *(const float4*)(sm + OFF_GX + 64 + nb);
        float4 x2b = *(const float4*)(sm + OFF_GX + 64 + nb + 4);
        float gx0[8] = {x0a.x, x0a.y, x0a.z, x0a.w, x0b.x, x0b.y, x0b.z, x0b.w};
        float gx1[8] = {x1a.x, x1a.y, x1a.z, x1a.w, x1b.x, x1b.y, x1b.z, x1b.w};
        float gx2[8] = {x2a.x, x2a.y, x2a.z, x2a.w, x2b.x, x2b.y, x2b.z, x2b.w};
        float4 pwa = __ldg((const float4*)(pos_w + o_base * 3));
        float4 pwb = __ldg((const float4*)(pos_w + o_base * 3 + 4));
        float4 pwc = __ldg((const float4*)(pos_w + o_base * 3 + 8));
        float pw[4][3] = {{pwa.x, pwa.y, pwa.z}, {pwa.w, pwb.x, pwb.y},
                          {pwb.z, pwb.w, pwc.x}, {pwc.y, pwc.z, pwc.w}};
        float ps[4], ks[4], pks[4];
        #pragma unroll
        for (int i = 0; i < 4; i++) {
            float a = 0.f, b = 0.f, c2 = 0.f;
            #pragma unroll
            for (int j = 0; j < 8; j++) {
                float pn = fmaxf(fmaf(pw[i][0], gx0[j],
                              fmaf(pw[i][1], gx1[j], pw[i][2] * gx2[j])), 0.f);
                a += pn; b += key_f[i][j]; c2 += pn * key_f[i][j];
            }
            ps[i] = a; ks[i] = b; pks[i] = c2;
        }
        #pragma unroll
        for (int i = 0; i < 4; i++) {
            #pragma unroll
            for (int d = 1; d <= 2; d <<= 1) {
                ps[i]  += __shfl_xor_sync(~0u, ps[i],  d);
                ks[i]  += __shfl_xor_sync(~0u, ks[i],  d);
                pks[i] += __shfl_xor_sync(~0u, pks[i], d);
            }
        }
        int ow = o_base + nq;
        float psw  = nq == 0 ? ps[0]  : nq == 1 ? ps[1]  : nq == 2 ? ps[2]  : ps[3];
        float ksw  = nq == 0 ? ks[0]  : nq == 1 ? ks[1]  : nq == 2 ? ks[2]  : ks[3];
        float pksw = nq == 0 ? pks[0] : nq == 1 ? pks[1] : nq == 2 ? pks[2] : pks[3];
        sm[OFF_MI + ow * 4 + 0] = psw  * (1.f / 32.f);
        sm[OFF_MI + ow * 4 + 1] = ksw  * (1.f / 32.f);
        sm[OFF_MI + ow * 4 + 2] = pksw * (1.f / 32.f);
    }
    __syncthreads();

    // ---- ctx matvecs (packed weights, 1 LDG.128 + 1 LDS.128 per c) ----
    {
        float av = 0.f, aq = 0.f, ak = 0.f, aqk = 0.f;
        const float4* cw = (const float4*)g_ctx4;
        #pragma unroll 4
        for (int c = 0; c < OD; c++) {
            float4 wv = __ldg(cw + c * 256 + tid);
            float4 mi = *(const float4*)(sm + OFF_MI + c * 4);
            av  = fmaf(mi.x, wv.x, av);
            aq  = fmaf(mi.x, wv.y, aq);
            ak  = fmaf(mi.y, wv.z, ak);
            aqk = fmaf(mi.z, wv.w, aqk);
        }
        sm[OFF_CTX + tid]       = sigf(av);
        sm[OFF_CTX + 256 + tid] = sigf(aq);
        sm[OFF_CTX + 512 + tid] = sigf(ak);
        sm[OFF_CTX + 768 + tid] = sigf(aqk);
    }

    // ---- val2 GEMM (4 o x 8 n, n-pair accumulators) ----
    ull wa[4][4];
    #pragma unroll
    for (int i = 0; i < 4; i++)
        #pragma unroll
        for (int j = 0; j < 4; j++) wa[i][j] = 0ull;
    {
        const float4* w2p = (const float4*)(g_v2T + o_base);
        float4 w0 = __ldg(w2p), w1 = __ldg(w2p + 64);
        for (int c = 0; c < OD; c++) {
            float4 w2 = __ldg(w2p + (c + 2) * 64);   // zero-padded rows
            const ulonglong2* vr = (const ulonglong2*)(sm + OFF_VB + c * 36 + nb);
            ulonglong2 va_ = vr[0], vb_ = vr[1];
            ull vp[4] = {va_.x, va_.y, vb_.x, vb_.y};
            ull p0 = pack2(w0.x), p1 = pack2(w0.y), p2 = pack2(w0.z), p3 = pack2(w0.w);
            #pragma unroll
            for (int j = 0; j < 4; j++) {
                ffma2(wa[0][j], p0, vp[j]);
                ffma2(wa[1][j], p1, vp[j]);
                ffma2(wa[2][j], p2, vp[j]);
                ffma2(wa[3][j], p3, vp[j]);
            }
            w0 = w1; w1 = w2;
        }
    }
    __syncthreads();     // all VB reads done; CTX visible

    // ---- epilogue 2: val regs + attn_emb -> VB (reuse) ----
    float val_f[4][8];
    {
        float4 g2 = __ldg((const float4*)(bn2g + o_base));
        float4 b2 = __ldg((const float4*)(bn2b + o_base));
        float g2a[4] = {g2.x, g2.y, g2.z, g2.w};
        float b2a[4] = {b2.x, b2.y, b2.z, b2.w};
        float4 cvc  = *(const float4*)(sm + OFF_CTX + o_base);
        float4 cqc  = *(const float4*)(sm + OFF_CTX + 256 + o_base);
        float4 ckc  = *(const float4*)(sm + OFF_CTX + 512 + o_base);
        float4 cqkc = *(const float4*)(sm + OFF_CTX + 768 + o_base);
        float vca[4]  = {cvc.x, cvc.y, cvc.z, cvc.w};
        float qca[4]  = {cqc.x, cqc.y, cqc.z, cqc.w};
        float kca[4]  = {ckc.x, ckc.y, ckc.z, ckc.w};
        float qkca[4] = {cqkc.x, cqkc.y, cqkc.z, cqkc.w};
        float4 x0a = *(const float4*)(sm + OFF_GX + nb);
        float4 x0b = *(const float4*)(sm + OFF_GX + nb + 4);
        float4 x1a = *(const float4*)(sm + OFF_GX + 32 + nb);
        float4 x1b = *(const float4*)(sm + OFF_GX + 32 + nb + 4);
        float4 x2a = *(const float4*)(sm + OFF_GX + 64 + nb);
        float4 x2b = *(const float4*)(sm + OFF_GX + 64 + nb + 4);
        float gx0[8] = {x0a.x, x0a.y, x0a.z, x0a.w, x0b.x, x0b.y, x0b.z, x0b.w};
        float gx1[8] = {x1a.x, x1a.y, x1a.z, x1a.w, x1b.x, x1b.y, x1b.z, x1b.w};
        float gx2[8] = {x2a.x, x2a.y, x2a.z, x2a.w, x2b.x, x2b.y, x2b.z, x2b.w};
        float4 pwa = __ldg((const float4*)(pos_w + o_base * 3));
        float4 pwb = __ldg((const float4*)(pos_w + o_base * 3 + 4));
        float4 pwc = __ldg((const float4*)(pos_w + o_base * 3 + 8));
        float pw[4][3] = {{pwa.x, pwa.y, pwa.z}, {pwa.w, pwb.x, pwb.y},
                          {pwb.z, pwb.w, pwc.x}, {pwc.y, pwc.z, pwc.w}};
        #pragma unroll
        for (int i = 0; i < 4; i++) {
            float raw[8];
            #pragma unroll
            for (int j2 = 0; j2 < 4; j2++) {
                float2 u = unpack2(wa[i][j2]);
                raw[2 * j2] = u.x; raw[2 * j2 + 1] = u.y;
            }
            float emb[8];
            #pragma unroll
            for (int j = 0; j < 8; j++) {
                float pn = fmaxf(fmaf(pw[i][0], gx0[j],
                              fmaf(pw[i][1], gx1[j], pw[i][2] * gx2[j])), 0.f);
                val_f[i][j] = fmaxf(fmaf(g2a[i], raw[j] * BNS, b2a[i]), 0.f) + pn * vca[i];
                emb[j] = fmaf(pn, qca[i],
                          fmaf(key_f[i][j], kca[i], (pn * key_f[i][j]) * qkca[i]));
            }
            float* dst = sm + OFF_VB + (o_base + i) * 36 + nb;
            *(float4*)(dst)     = make_float4(emb[0], emb[1], emb[2], emb[3]);
            *(float4*)(dst + 4) = make_float4(emb[4], emb[5], emb[6], emb[7]);
        }
    }
    __syncthreads();

    // ---- logits partials: warp w covers o rows [w*32, w*32+32) ----
    {
        float a0 = 0.f, a1 = 0.f, a2 = 0.f, a3 = 0.f;
        #pragma unroll 4
        for (int c = w * 32; c < w * 32 + 32; c++) {
            float x = sm[OFF_VB + c * 36 + l];
            float4 aw = *(const float4*)(sm + OFF_AWI + c * 4);
            a0 = fmaf(aw.x, x, a0); a1 = fmaf(aw.y, x, a1);
            a2 = fmaf(aw.z, x, a2); a3 = fmaf(aw.w, x, a3);
        }
        sm[OFF_PART + w * 128 +       l] = a0;
        sm[OFF_PART + w * 128 +  32 + l] = a1;
        sm[OFF_PART + w * 128 +  64 + l] = a2;
        sm[OFF_PART + w * 128 +  96 + l] = a3;
    }
    __syncthreads();

    // ---- softmax (warps 0..3, h = w) ----
    if (w < 4) {
        float s = 0.f;
        #pragma unroll
        for (int ww = 0; ww < 8; ww++) s += sm[OFF_PART + ww * 128 + w * 32 + l];
        float mx = s;
        #pragma unroll
        for (int d = 16; d; d >>= 1) mx = fmaxf(mx, __shfl_xor_sync(~0u, mx, d));
        float e = expf(s - mx);
        float den = e;
        #pragma unroll
        for (int d = 16; d; d >>= 1) den += __shfl_xor_sync(~0u, den, d);
        sm[OFF_ATT + w * 32 + l] = e / den;
    }
    __syncthreads();

    // ---- new_features = sum_n val*attn (quad butterfly) ----
    {
        int h = o_base >> 6;
        float4 a0 = *(const float4*)(sm + OFF_ATT + h * 32 + nb);
        float4 a1 = *(const float4*)(sm + OFF_ATT + h * 32 + nb + 4);
        float at[8] = {a0.x, a0.y, a0.z, a0.w, a1.x, a1.y, a1.z, a1.w};
        float s[4];
        #pragma unroll
        for (int i = 0; i < 4; i++) {
            float a = 0.f;
            #pragma unroll
            for (int j = 0; j < 8; j++) a = fmaf(val_f[i][j], at[j], a);
            s[i] = a;
        }
        #pragma unroll
        for (int i = 0; i < 4; i++) {
            #pragma unroll
            for (int d = 1; d <= 2; d <<= 1) s[i] += __shfl_xor_sync(~0u, s[i], d);
        }
        int ow = o_base + nq;
        float sv = nq == 0 ? s[0] : nq == 1 ? s[1] : nq == 2 ? s[2] : s[3];
        sm[OFF_NF + ow] = sv;
        out[(size_t)m * OD + ow] = sv;
    }
    __syncthreads();

    // ---- gate hidden (packed 4-c weights) ----
    {
        int t = tid & 127;
        float acc = (tid >= 128) ? __ldg(rb1 + t) : __ldg(cb1 + t);
        const float4* gw = (const float4*)g_gate4;
        #pragma unroll 4
        for (int c4 = 0; c4 < 64; c4++) {
            float4 wv = __ldg(gw + c4 * 256 + tid);
            float4 nf4 = *(const float4*)(sm + OFF_NF + c4 * 4);
            acc = fmaf(nf4.x, wv.x, fmaf(nf4.y, wv.y,
                  fmaf(nf4.z, wv.z, fmaf(nf4.w, wv.w, acc))));
        }
        sm[OFF_HID + tid] = fmaxf(acc, 0.f);
    }
    __syncthreads();
    if (w < 2) {
        const float* hid = sm + OFF_HID + w * 128;
        const float* w2v = w ? rw2 : cw2;
        float s = 0.f;
        #pragma unroll
        for (int k = 0; k < 4; k++)
            s = fmaf(hid[l + 32 * k], __ldg(w2v + l + 32 * k), s);
        #pragma unroll
        for (int d = 16; d; d >>= 1) s += __shfl_xor_sync(~0u, s, d);
        if (l == 0) sm[OFF_MISC + 4 + w] = sigf(s + __ldg(w ? rb2 : cb2));
    }
    __syncthreads();
    {
        float nf = sm[OFF_NF + tid];
        out[(size_t)MQ * OD + (size_t)m * OD + tid]     = nf * sm[OFF_MISC + 4];
        out[(size_t)2 * MQ * OD + (size_t)m * OD + tid] = nf * sm[OFF_MISC + 5];
    }
}

// ---------------- launch ------------------------------------------------------
extern "C" void kernel_launch(void* const* d_in, const int* in_sizes, int n_in,
                              void* d_out, int out_size) {
    const float* xyz   = (const float*)d_in[0];
    const float* nxyz  = (const float*)d_in[1];
    const float* feats = (const float*)d_in[2];
    const float* pos_w = (const float*)d_in[3];
    const float* key_w = (const float*)d_in[4];
    const float* v1w   = (const float*)d_in[5];
    const float* bn1g  = (const float*)d_in[6];
    const float* bn1b  = (const float*)d_in[7];
    const float* v2w   = (const float*)d_in[8];
    const float* bn2g  = (const float*)d_in[9];
    const float* bn2b  = (const float*)d_in[10];
    const float* attnw = (const float*)d_in[11];
    const float* kcw   = (const float*)d_in[12];
    const float* qcw   = (const float*)d_in[13];
    const float* qkcw  = (const float*)d_in[14];
    const float* vcw   = (const float*)d_in[15];
    const float* cw1   = (const float*)d_in[16];
    const float* cb1   = (const float*)d_in[17];
    const float* cw2   = (const float*)d_in[18];
    const float* cb2   = (const float*)d_in[19];
    const float* rw1   = (const float*)d_in[20];
    const float* rb1   = (const float*)d_in[21];
    const float* rw2   = (const float*)d_in[22];
    const float* rb2   = (const float*)d_in[23];
    float* out = (float*)d_out;

    static bool attr_set = false;
    if (!attr_set) {
        cudaFuncSetAttribute(main_kernel, cudaFuncAttributeMaxDynamicSharedMemorySize,
                             SM_FLOATS * 4);
        attr_set = true;
    }

    wprep_kernel<<<256, 256>>>(key_w, v1w, v2w, kcw, qcw, qkcw, vcw, cw1, rw1);
    tfeat_kernel<<<dim3(256, 4, 2), dim3(32, 8)>>>(feats);
    ball_kernel<<<MQ / 8, 256>>>(xyz, nxyz);
    main_kernel<<<MQ, 256, SM_FLOATS * 4>>>(xyz, nxyz, pos_w, bn1g, bn1b, bn2g, bn2b,
                                            attnw, cb1, cw2, cb2, rb1, rw2, rb2, out);
}